// round 11
// baseline (speedup 1.0000x reference)
#include <cuda_runtime.h>
#include <cuda_bf16.h>
#include <math.h>

// out[i] = mean_{p != i} ( tanh( [x_i, x_p] @ W1 + b1 ) @ W2 + b2 )
// A = x@W1[:64] + b1, B = x@W1[64:]
// S[i,h] = sum_p tanh(A[i,h]+B[p,h])  via separable 2D-Chebyshev expansion:
//   tanh(a+b) ~= sum_{j,k} C_jk T_j(a/D) T_k(b/D)
//   M_k[h] = sum_p T_k(B~[p,h]);  R_j[h] = sum_k C_jk M_k[h]
//   S[i,h] = sum_j T_j(A~[i,h]) R_j[h]
// out[i] = ((S[i] - tanh(A[i]+B[i])) / 1023) @ W2 + b2

#define N_E    1024
#define N_IN   64
#define HIDDEN 128
#define OUTD   64

#define DEG    48               // Chebyshev degree (inclusive)
#define NC     (DEG + 1)        // 49 coefficients per dim
#define NQ     64               // quadrature nodes per dim
#define DDOM   5.0f             // expansion domain [-D, D] per variable

#define TI1    8                // i-rows per block, phase 1
#define FSPLIT 4                // f-dim split, phase 1
#define FPT    (N_IN / FSPLIT)  // 16
#define TI4    4                // i-rows per i-group, main kernel
#define TI3    8                // i-rows per block, phase 3

// Scratch (device globals — no runtime allocation allowed)
__device__ float g_A[N_E * HIDDEN];        // 512 KB
__device__ float g_B[N_E * HIDDEN];        // 512 KB
__device__ float g_S[N_E * HIDDEN];        // 512 KB
__device__ float g_F[NQ * NQ];             // tanh at 2D Chebyshev nodes
__device__ float g_cosT[NC * NQ];          // cos(j * theta_p)
__device__ float g_C[NC * NC];             // 2D Chebyshev coefficients
__device__ float g_R[NC * HIDDEN];         // per-h reduced coefficients

__device__ __forceinline__ float tanh_fast(float x) {
    float y;
    asm("tanh.approx.f32 %0, %1;" : "=f"(y) : "f"(x));
    return y;
}

// ---------------------------------------------------------------------------
// Kernel A: phase1 (A,B GEMMs) + node tables (2 extra blocks).
// Blocks [0,128): 8 i-rows each, f-dim split 4 ways across 512 threads.
// Block 128: cos table. Block 129: tanh at nodes (double precision).
// ---------------------------------------------------------------------------
__global__ void __launch_bounds__(FSPLIT * HIDDEN) kA_phase1_nodes(
    const float* __restrict__ x, const float* __restrict__ W1,
    const float* __restrict__ b1)
{
    const int t = threadIdx.x;

    if (blockIdx.x == (N_E / TI1)) {
        // cosT[j*NQ + p] = cos(j * theta_p), theta_p = (p+0.5)*pi/NQ
        for (int idx = t; idx < NC * NQ; idx += FSPLIT * HIDDEN) {
            const int j = idx / NQ, p = idx % NQ;
            const double th = (p + 0.5) * (3.14159265358979323846 / NQ);
            g_cosT[idx] = (float)cos((double)j * th);
        }
        return;
    }
    if (blockIdx.x == (N_E / TI1) + 1) {
        // f[p*NQ + q] = tanh(D*(x_p + x_q)), x_p = cos(theta_p)
        for (int idx = t; idx < NQ * NQ; idx += FSPLIT * HIDDEN) {
            const int p = idx / NQ, q = idx % NQ;
            const double thp = (p + 0.5) * (3.14159265358979323846 / NQ);
            const double thq = (q + 0.5) * (3.14159265358979323846 / NQ);
            g_F[idx] = (float)tanh((double)DDOM * (cos(thp) + cos(thq)));
        }
        return;
    }

    const int h  = t & (HIDDEN - 1);
    const int fg = t >> 7;                 // f-group 0..3
    const int i0 = blockIdx.x * TI1;

    __shared__ float xs[TI1][N_IN];                          // 2 KB
    __shared__ float red[FSPLIT][2][TI1][HIDDEN];            // 32 KB

    xs[t >> 6][t & 63] = x[i0 * N_IN + t];                   // 512 elems
    __syncthreads();

    float a[TI1], b[TI1];
    #pragma unroll
    for (int k = 0; k < TI1; k++) { a[k] = 0.0f; b[k] = 0.0f; }

    const int fbase = fg * FPT;
    #pragma unroll
    for (int ff = 0; ff < FPT; ff++) {
        const int f = fbase + ff;
        const float wa = W1[f * HIDDEN + h];
        const float wb = W1[(N_IN + f) * HIDDEN + h];
        #pragma unroll
        for (int k = 0; k < TI1; k++) {
            const float xv = xs[k][f];
            a[k] = fmaf(xv, wa, a[k]);
            b[k] = fmaf(xv, wb, b[k]);
        }
    }

    #pragma unroll
    for (int k = 0; k < TI1; k++) {
        red[fg][0][k][h] = a[k];
        red[fg][1][k][h] = b[k];
    }
    __syncthreads();

    if (fg == 0) {
        const float bb = b1[h];
        #pragma unroll
        for (int k = 0; k < TI1; k++) {
            float av = a[k] + red[1][0][k][h] + red[2][0][k][h] + red[3][0][k][h];
            float bv = b[k] + red[1][1][k][h] + red[2][1][k][h] + red[3][1][k][h];
            g_A[(i0 + k) * HIDDEN + h] = av + bb;
            g_B[(i0 + k) * HIDDEN + h] = bv;
        }
    }
}

// ---------------------------------------------------------------------------
// Kernel B: separable 2D DCT -> coefficients C_jk (double accumulation).
// One block per j (49 blocks, 64 threads).
//   G[q]   = sum_p f[p][q] * cos(j theta_p)
//   C[j][k]= w_j w_k / NQ^2 * sum_q G[q] * cos(k theta_q)
// ---------------------------------------------------------------------------
__global__ void __launch_bounds__(NQ) kB_dct()
{
    const int j = blockIdx.x;
    const int t = threadIdx.x;

    __shared__ double Gq[NQ];

    double g = 0.0;
    #pragma unroll 8
    for (int p = 0; p < NQ; p++)
        g += (double)g_F[p * NQ + t] * (double)g_cosT[j * NQ + p];
    Gq[t] = g;
    __syncthreads();

    if (t < NC) {
        double c = 0.0;
        #pragma unroll 8
        for (int q = 0; q < NQ; q++)
            c += Gq[q] * (double)g_cosT[t * NQ + q];
        const double wj = (j == 0) ? 1.0 : 2.0;
        const double wk = (t == 0) ? 1.0 : 2.0;
        g_C[j * NC + t] = (float)(c * wj * wk / ((double)NQ * NQ));
    }
}

// ---------------------------------------------------------------------------
// Kernel C: moments M_k[h] = sum_p T_k(B~[p,h]) and R_j[h] = sum_k C_jk M_k[h].
// One block per h (128 blocks, 64 threads); each thread covers 16 p's.
// ---------------------------------------------------------------------------
__global__ void __launch_bounds__(64) kC_moments()
{
    const int h = blockIdx.x;
    const int t = threadIdx.x;
    const float invD = 1.0f / DDOM;

    float m[NC];
    #pragma unroll
    for (int k = 0; k < NC; k++) m[k] = 0.0f;

    for (int r = 0; r < N_E / 64; r++) {
        const int p = r * 64 + t;
        float xv = g_B[p * HIDDEN + h] * invD;
        xv = fminf(fmaxf(xv, -1.0f), 1.0f);
        float tp = 1.0f, tc = xv;
        m[0] += 1.0f;
        m[1] += xv;
        const float x2 = 2.0f * xv;
        #pragma unroll
        for (int k = 2; k < NC; k++) {
            const float tn = fmaf(x2, tc, -tp);
            m[k] += tn;
            tp = tc; tc = tn;
        }
    }

    __shared__ float red[64][NC];          // 12.5 KB
    __shared__ float Msh[NC];
    #pragma unroll
    for (int k = 0; k < NC; k++) red[t][k] = m[k];
    __syncthreads();

    if (t < NC) {
        float s = 0.0f;
        #pragma unroll 8
        for (int r = 0; r < 64; r++) s += red[r][t];
        Msh[t] = s;
    }
    __syncthreads();

    if (t < NC) {
        float rj = 0.0f;
        #pragma unroll 7
        for (int k = 0; k < NC; k++)
            rj = fmaf(g_C[t * NC + k], Msh[k], rj);
        g_R[t * HIDDEN + h] = rj;
    }
}

// ---------------------------------------------------------------------------
// Kernel D: S[i,h] = sum_j T_j(A~[i,h]) * R_j[h].
// 128 blocks x 256 threads: thread = (h, i-group of 2); 4 i-rows per group.
// R staged in shared (25 KB), inner loop = 2 FMA per (j, i).
// ---------------------------------------------------------------------------
__global__ void __launch_bounds__(256) kD_main()
{
    const int t  = threadIdx.x;
    const int h  = t & (HIDDEN - 1);
    const int ig = t >> 7;
    const int i0 = blockIdx.x * (2 * TI4) + ig * TI4;
    const float invD = 1.0f / DDOM;

    __shared__ float sR[NC * HIDDEN];      // 24.5 KB, layout j*128+h
    for (int idx = t; idx < NC * HIDDEN; idx += 256)
        sR[idx] = g_R[idx];
    __syncthreads();

    float xv[TI4], x2[TI4], tp[TI4], tc[TI4], s[TI4];
    const float r0 = sR[0 * HIDDEN + h];
    const float r1 = sR[1 * HIDDEN + h];
    #pragma unroll
    for (int k = 0; k < TI4; k++) {
        float a = g_A[(i0 + k) * HIDDEN + h] * invD;
        a = fminf(fmaxf(a, -1.0f), 1.0f);
        xv[k] = a; x2[k] = 2.0f * a;
        tp[k] = 1.0f; tc[k] = a;
        s[k]  = fmaf(r1, a, r0);
    }

    #pragma unroll
    for (int j = 2; j < NC; j++) {
        const float rj = sR[j * HIDDEN + h];
        #pragma unroll
        for (int k = 0; k < TI4; k++) {
            const float tn = fmaf(x2[k], tc[k], -tp[k]);
            s[k] = fmaf(rj, tn, s[k]);
            tp[k] = tc[k]; tc[k] = tn;
        }
    }

    #pragma unroll
    for (int k = 0; k < TI4; k++)
        g_S[(i0 + k) * HIDDEN + h] = s[k];
}

// ---------------------------------------------------------------------------
// Kernel E: subtract self term, scale, project through W2, add b2.
// 8 entities per block; W2 read once per 8 i; transposed shared for float4 LDS.
// ---------------------------------------------------------------------------
__global__ void __launch_bounds__(128) kE_out(
    const float* __restrict__ W2, const float* __restrict__ b2,
    float* __restrict__ out)
{
    const int i0 = blockIdx.x * TI3;
    const int t  = threadIdx.x;

    __shared__ __align__(16) float s2[HIDDEN][TI3];   // 4 KB
    __shared__ float po[2][TI3][OUTD];                // 4 KB

    #pragma unroll
    for (int ii = 0; ii < TI3; ii++) {
        const int i = i0 + ii;
        const float v = g_S[i * HIDDEN + t];
        const float self_t = tanh_fast(g_A[i * HIDDEN + t] + g_B[i * HIDDEN + t]);
        s2[t][ii] = (v - self_t) * (1.0f / (float)(N_E - 1));
    }
    __syncthreads();

    const int o    = t & (OUTD - 1);
    const int half = t >> 6;
    float acc[TI3];
    #pragma unroll
    for (int ii = 0; ii < TI3; ii++) acc[ii] = 0.0f;

    #pragma unroll 8
    for (int hh = 0; hh < HIDDEN / 2; hh++) {
        const int hid = half * (HIDDEN / 2) + hh;
        const float w = W2[hid * OUTD + o];
        const float4 sa = *(const float4*)&s2[hid][0];
        const float4 sb = *(const float4*)&s2[hid][4];
        acc[0] = fmaf(sa.x, w, acc[0]);
        acc[1] = fmaf(sa.y, w, acc[1]);
        acc[2] = fmaf(sa.z, w, acc[2]);
        acc[3] = fmaf(sa.w, w, acc[3]);
        acc[4] = fmaf(sb.x, w, acc[4]);
        acc[5] = fmaf(sb.y, w, acc[5]);
        acc[6] = fmaf(sb.z, w, acc[6]);
        acc[7] = fmaf(sb.w, w, acc[7]);
    }

    #pragma unroll
    for (int ii = 0; ii < TI3; ii++) po[half][ii][o] = acc[ii];
    __syncthreads();

    if (t < OUTD) {
        const float bb = b2[t];
        #pragma unroll
        for (int ii = 0; ii < TI3; ii++)
            out[(i0 + ii) * OUTD + t] = po[0][ii][t] + po[1][ii][t] + bb;
    }
}

// ---------------------------------------------------------------------------
extern "C" void kernel_launch(void* const* d_in, const int* in_sizes, int n_in,
                              void* d_out, int out_size)
{
    // Map inputs by element count (all distinct): x=65536, W1=16384, b1=128,
    // W2=8192, b2=64.
    const float *x = nullptr, *W1 = nullptr, *b1 = nullptr, *W2 = nullptr, *b2 = nullptr;
    for (int i = 0; i < n_in; i++) {
        switch (in_sizes[i]) {
            case N_E * N_IN:          x  = (const float*)d_in[i]; break;
            case 2 * N_IN * HIDDEN:   W1 = (const float*)d_in[i]; break;
            case HIDDEN:              b1 = (const float*)d_in[i]; break;
            case HIDDEN * OUTD:       W2 = (const float*)d_in[i]; break;
            case OUTD:                b2 = (const float*)d_in[i]; break;
            default: break;
        }
    }
    float* out = (float*)d_out;

    kA_phase1_nodes<<<N_E / TI1 + 2, FSPLIT * HIDDEN>>>(x, W1, b1);
    kB_dct<<<NC, NQ>>>();
    kC_moments<<<HIDDEN, 64>>>();
    kD_main<<<N_E / (2 * TI4), 256>>>();
    kE_out<<<N_E / TI3, 128>>>(W2, b2, out);
}

// round 12
// speedup vs baseline: 4.8964x; 4.8964x over previous
#include <cuda_runtime.h>
#include <cuda_bf16.h>
#include <math.h>

// out[i] = mean_{p != i} ( tanh( [x_i, x_p] @ W1 + b1 ) @ W2 + b2 )
// A = x@W1[:64] + b1, B = x@W1[64:]
// S[i,h] = sum_p tanh(A[i,h]+B[p,h]) via separable 2D Chebyshev:
//   tanh(a+b) ~= sum_{j,k<=48} C_jk T_j(a/D) T_k(b/D)
//   M_k[h] = sum_p T_k(B~[p,h]);  R_j[h] = sum_k C_jk M_k[h]
//   S[i,h] = sum_j T_j(A~[i,h]) R_j[h]
// out[i] = ((S[i] - tanh(A[i]+B[i])) / 1023) @ W2 + b2

#define N_E    1024
#define N_IN   64
#define HIDDEN 128
#define OUTD   64

#define DEG    48
#define NC     (DEG + 1)        // 49
#define NQ     64
#define DDOM   5.0f

#define TI1    2                // i-rows per block, phase 1 (proven config)
#define FSPLIT 4
#define FPT    (N_IN / FSPLIT)  // 16
#define TI4    4                // i-rows per block, fused main kernel

// Scratch (device globals — no runtime allocation allowed)
__device__ float g_A[N_E * HIDDEN];
__device__ float g_B[N_E * HIDDEN];
__device__ float g_F[NQ * NQ];
__device__ float g_cosT[NC * NQ];
__device__ float g_C[NC * NC];
__device__ float g_R[NC * HIDDEN];

__device__ __forceinline__ float tanh_fast(float x) {
    float y;
    asm("tanh.approx.f32 %0, %1;" : "=f"(y) : "f"(x));
    return y;
}

// ---------------------------------------------------------------------------
// K1: phase1 GEMMs (blocks [0,512)) + node tables (blocks 512, 513).
// ---------------------------------------------------------------------------
__global__ void __launch_bounds__(FSPLIT * HIDDEN) k1_phase1_tables(
    const float* __restrict__ x, const float* __restrict__ W1,
    const float* __restrict__ b1)
{
    const int t = threadIdx.x;

    if (blockIdx.x == (N_E / TI1)) {
        // cosT[j*NQ+p] = cos(j*theta_p) via double recurrence (1 double cos).
        if (t < NQ) {
            const double th = (t + 0.5) * (3.14159265358979323846 / NQ);
            const double c1 = cos(th);
            double cm = 1.0, cc = c1;
            g_cosT[0 * NQ + t] = 1.0f;
            g_cosT[1 * NQ + t] = (float)c1;
            for (int j = 2; j < NC; j++) {
                const double cn = 2.0 * c1 * cc - cm;
                g_cosT[j * NQ + t] = (float)cn;
                cm = cc; cc = cn;
            }
        }
        return;
    }
    if (blockIdx.x == (N_E / TI1) + 1) {
        // F[p*NQ+q] = tanh(D*(x_p + x_q)); nodes in double, tanh in float.
        __shared__ float xn[NQ];
        if (t < NQ) {
            const double th = (t + 0.5) * (3.14159265358979323846 / NQ);
            xn[t] = (float)cos(th);
        }
        __syncthreads();
        for (int idx = t; idx < NQ * NQ; idx += FSPLIT * HIDDEN) {
            const int p = idx >> 6, q = idx & 63;
            g_F[idx] = tanhf(DDOM * (xn[p] + xn[q]));
        }
        return;
    }

    const int h  = t & (HIDDEN - 1);
    const int fg = t >> 7;
    const int i0 = blockIdx.x * TI1;

    __shared__ float xs[TI1][N_IN];
    __shared__ float red[FSPLIT][2][TI1][HIDDEN];   // 8 KB

    if (t < TI1 * N_IN) xs[t >> 6][t & 63] = x[i0 * N_IN + t];
    __syncthreads();

    float a[TI1], b[TI1];
    #pragma unroll
    for (int k = 0; k < TI1; k++) { a[k] = 0.0f; b[k] = 0.0f; }

    const int fbase = fg * FPT;
    #pragma unroll
    for (int ff = 0; ff < FPT; ff++) {
        const int f = fbase + ff;
        const float wa = W1[f * HIDDEN + h];
        const float wb = W1[(N_IN + f) * HIDDEN + h];
        #pragma unroll
        for (int k = 0; k < TI1; k++) {
            const float xv = xs[k][f];
            a[k] = fmaf(xv, wa, a[k]);
            b[k] = fmaf(xv, wb, b[k]);
        }
    }

    #pragma unroll
    for (int k = 0; k < TI1; k++) {
        red[fg][0][k][h] = a[k];
        red[fg][1][k][h] = b[k];
    }
    __syncthreads();

    if (fg == 0) {
        const float bb = b1[h];
        #pragma unroll
        for (int k = 0; k < TI1; k++) {
            float av = a[k] + red[1][0][k][h] + red[2][0][k][h] + red[3][0][k][h];
            float bv = b[k] + red[1][1][k][h] + red[2][1][k][h] + red[3][1][k][h];
            g_A[(i0 + k) * HIDDEN + h] = av + bb;
            g_B[(i0 + k) * HIDDEN + h] = bv;
        }
    }
}

// ---------------------------------------------------------------------------
// K2: separable 2D DCT -> C_jk. One block per j (49 x 64 threads).
// Double accumulation, chains broken 4-way for DFMA-latency.
// ---------------------------------------------------------------------------
__global__ void __launch_bounds__(NQ) k2_dct()
{
    const int j = blockIdx.x;
    const int t = threadIdx.x;

    __shared__ double Gq[NQ];

    double g0 = 0.0, g1 = 0.0, g2 = 0.0, g3 = 0.0;
    #pragma unroll
    for (int p = 0; p < NQ; p += 4) {
        g0 += (double)g_F[(p + 0) * NQ + t] * (double)g_cosT[j * NQ + p + 0];
        g1 += (double)g_F[(p + 1) * NQ + t] * (double)g_cosT[j * NQ + p + 1];
        g2 += (double)g_F[(p + 2) * NQ + t] * (double)g_cosT[j * NQ + p + 2];
        g3 += (double)g_F[(p + 3) * NQ + t] * (double)g_cosT[j * NQ + p + 3];
    }
    Gq[t] = (g0 + g1) + (g2 + g3);
    __syncthreads();

    if (t < NC) {
        double c0 = 0.0, c1 = 0.0;
        #pragma unroll
        for (int q = 0; q < NQ; q += 2) {
            c0 += Gq[q]     * (double)g_cosT[t * NQ + q];
            c1 += Gq[q + 1] * (double)g_cosT[t * NQ + q + 1];
        }
        const double wj = (j == 0) ? 1.0 : 2.0;
        const double wk = (t == 0) ? 1.0 : 2.0;
        g_C[j * NC + t] = (float)((c0 + c1) * wj * wk / ((double)NQ * NQ));
    }
}

// ---------------------------------------------------------------------------
// K3: fused moments + reduce: M_k[h] = sum_p T_k(B~[p,h]); R_j[h] = sum_k C_jk M_k[h].
// One block per h, 512 threads, 2 p's per thread, warp-shuffle reduce.
// ---------------------------------------------------------------------------
__global__ void __launch_bounds__(512) k3_moments()
{
    const int h    = blockIdx.x;
    const int t    = threadIdx.x;
    const int lane = t & 31;
    const int wid  = t >> 5;              // 16 warps
    const float invD = 1.0f / DDOM;

    float m[NC];
    #pragma unroll
    for (int k = 0; k < NC; k++) m[k] = 0.0f;

    #pragma unroll
    for (int r = 0; r < 2; r++) {
        const int p = r * 512 + t;
        float xv = g_B[p * HIDDEN + h] * invD;
        xv = fminf(fmaxf(xv, -1.0f), 1.0f);
        float tp = 1.0f, tc = xv;
        m[0] += 1.0f;
        m[1] += xv;
        const float x2 = 2.0f * xv;
        #pragma unroll
        for (int k = 2; k < NC; k++) {
            const float tn = fmaf(x2, tc, -tp);
            m[k] += tn;
            tp = tc; tc = tn;
        }
    }

    __shared__ float warp_red[16][NC];    // 3.1 KB
    __shared__ float Msh[NC];

    #pragma unroll
    for (int k = 0; k < NC; k++) {
        float v = m[k];
        v += __shfl_xor_sync(0xffffffff, v, 16);
        v += __shfl_xor_sync(0xffffffff, v, 8);
        v += __shfl_xor_sync(0xffffffff, v, 4);
        v += __shfl_xor_sync(0xffffffff, v, 2);
        v += __shfl_xor_sync(0xffffffff, v, 1);
        if (lane == 0) warp_red[wid][k] = v;
    }
    __syncthreads();

    if (t < NC) {
        float s = 0.0f;
        #pragma unroll
        for (int w = 0; w < 16; w++) s += warp_red[w][t];
        Msh[t] = s;
    }
    __syncthreads();

    if (t < NC) {
        float r0 = 0.0f, r1 = 0.0f;
        #pragma unroll
        for (int k = 0; k < NC - 1; k += 2) {
            r0 = fmaf(g_C[t * NC + k],     Msh[k],     r0);
            r1 = fmaf(g_C[t * NC + k + 1], Msh[k + 1], r1);
        }
        r0 = fmaf(g_C[t * NC + NC - 1], Msh[NC - 1], r0);
        g_R[t * HIDDEN + h] = r0 + r1;
    }
}

// ---------------------------------------------------------------------------
// K4: fused main: S[i,h] = sum_j T_j(A~) R_j[h]; subtract self tanh, scale,
// project through W2, add b2. Block = 4 i-rows x 128 h-threads; 256 blocks.
// ---------------------------------------------------------------------------
__global__ void __launch_bounds__(HIDDEN) k4_main(
    const float* __restrict__ W2, const float* __restrict__ b2,
    float* __restrict__ out)
{
    const int t  = threadIdx.x;           // = h
    const int i0 = blockIdx.x * TI4;
    const float invD = 1.0f / DDOM;

    __shared__ __align__(16) float s2[HIDDEN][TI4];   // 2 KB
    __shared__ float po[2][TI4][OUTD];                // 2 KB

    // Chebyshev evaluation for 4 i-rows (independent recurrences -> 4-way ILP)
    float araw[TI4], xv[TI4], x2[TI4], tp[TI4], tc[TI4], s[TI4];
    const float r0 = __ldg(&g_R[0 * HIDDEN + t]);
    const float r1 = __ldg(&g_R[1 * HIDDEN + t]);
    #pragma unroll
    for (int k = 0; k < TI4; k++) {
        araw[k] = g_A[(i0 + k) * HIDDEN + t];
        float a = araw[k] * invD;
        a = fminf(fmaxf(a, -1.0f), 1.0f);
        xv[k] = a; x2[k] = 2.0f * a;
        tp[k] = 1.0f; tc[k] = a;
        s[k]  = fmaf(r1, a, r0);
    }

    #pragma unroll
    for (int j = 2; j < NC; j++) {
        const float rj = __ldg(&g_R[j * HIDDEN + t]);
        #pragma unroll
        for (int k = 0; k < TI4; k++) {
            const float tn = fmaf(x2[k], tc[k], -tp[k]);
            s[k] = fmaf(rj, tn, s[k]);
            tp[k] = tc[k]; tc[k] = tn;
        }
    }

    // self term + scale
    #pragma unroll
    for (int k = 0; k < TI4; k++) {
        const float self_t = tanh_fast(araw[k] + g_B[(i0 + k) * HIDDEN + t]);
        s2[t][k] = (s[k] - self_t) * (1.0f / (float)(N_E - 1));
    }
    __syncthreads();

    // GEMV through W2 (hidden split in halves across the 128 threads)
    const int o    = t & (OUTD - 1);
    const int half = t >> 6;
    float acc[TI4];
    #pragma unroll
    for (int k = 0; k < TI4; k++) acc[k] = 0.0f;

    #pragma unroll 8
    for (int hh = 0; hh < HIDDEN / 2; hh++) {
        const int hid = half * (HIDDEN / 2) + hh;
        const float w = W2[hid * OUTD + o];
        const float4 sv = *(const float4*)&s2[hid][0];
        acc[0] = fmaf(sv.x, w, acc[0]);
        acc[1] = fmaf(sv.y, w, acc[1]);
        acc[2] = fmaf(sv.z, w, acc[2]);
        acc[3] = fmaf(sv.w, w, acc[3]);
    }

    #pragma unroll
    for (int k = 0; k < TI4; k++) po[half][k][o] = acc[k];
    __syncthreads();

    if (t < OUTD) {
        const float bb = b2[t];
        #pragma unroll
        for (int k = 0; k < TI4; k++)
            out[(i0 + k) * OUTD + t] = po[0][k][t] + po[1][k][t] + bb;
    }
}

// ---------------------------------------------------------------------------
extern "C" void kernel_launch(void* const* d_in, const int* in_sizes, int n_in,
                              void* d_out, int out_size)
{
    // Map inputs by element count (all distinct): x=65536, W1=16384, b1=128,
    // W2=8192, b2=64.
    const float *x = nullptr, *W1 = nullptr, *b1 = nullptr, *W2 = nullptr, *b2 = nullptr;
    for (int i = 0; i < n_in; i++) {
        switch (in_sizes[i]) {
            case N_E * N_IN:          x  = (const float*)d_in[i]; break;
            case 2 * N_IN * HIDDEN:   W1 = (const float*)d_in[i]; break;
            case HIDDEN:              b1 = (const float*)d_in[i]; break;
            case HIDDEN * OUTD:       W2 = (const float*)d_in[i]; break;
            case OUTD:                b2 = (const float*)d_in[i]; break;
            default: break;
        }
    }
    float* out = (float*)d_out;

    k1_phase1_tables<<<N_E / TI1 + 2, FSPLIT * HIDDEN>>>(x, W1, b1);
    k2_dct<<<NC, NQ>>>();
    k3_moments<<<HIDDEN, 512>>>();
    k4_main<<<N_E / TI4, HIDDEN>>>(W2, b2, out);
}

// round 13
// speedup vs baseline: 5.4990x; 1.1231x over previous
#include <cuda_runtime.h>
#include <cuda_bf16.h>
#include <math.h>

// out[i] = mean_{p != i} ( tanh( [x_i, x_p] @ W1 + b1 ) @ W2 + b2 )
// A = x@W1[:64] + b1, B = x@W1[64:]
// S[i,h] = sum_p tanh(A[i,h]+B[p,h]) via separable 2D Chebyshev:
//   tanh(a+b) ~= sum_{j,k<=DEG} C_jk T_j(a/D) T_k(b/D)
//   M_k[h] = sum_p T_k(B~[p,h]);  R_j[h] = sum_k C_jk M_k[h]
//   S[i,h] = sum_j T_j(A~[i,h]) R_j[h]
// out[i] = ((S[i] - tanh(A[i]+B[i])) / 1023) @ W2 + b2

#define N_E    1024
#define N_IN   64
#define HIDDEN 128
#define OUTD   64

#define DEG    40
#define NC     (DEG + 1)        // 41
#define NQ     64
#define DDOM   5.0f

#define TI1    4                // i-rows per block, phase 1
#define FSPLIT 4
#define FPT    (N_IN / FSPLIT)  // 16
#define TI4    2                // i-rows per block, fused main kernel

// Scratch (device globals — no runtime allocation allowed)
__device__ float g_A[N_E * HIDDEN];
__device__ float g_B[N_E * HIDDEN];
__device__ float g_F[NQ * NQ];
__device__ float g_cosT[NC * NQ];
__device__ float g_C[NC * NC];
__device__ float g_R[NC * HIDDEN];

__device__ __forceinline__ float tanh_fast(float x) {
    float y;
    asm("tanh.approx.f32 %0, %1;" : "=f"(y) : "f"(x));
    return y;
}

// ---------------------------------------------------------------------------
// K1: phase1 GEMMs (blocks [0,256)) + node tables (blocks 256, 257).
// 512 threads/block; f-dim split 4 ways, shared reduce; 4 i-rows per block
// halves W1 L2 traffic vs TI1=2.
// ---------------------------------------------------------------------------
__global__ void __launch_bounds__(FSPLIT * HIDDEN) k1_phase1_tables(
    const float* __restrict__ x, const float* __restrict__ W1,
    const float* __restrict__ b1)
{
    const int t = threadIdx.x;

    if (blockIdx.x == (N_E / TI1)) {
        // cosT[j*NQ+p] = cos(j*theta_p) via double recurrence (1 double cos).
        if (t < NQ) {
            const double th = (t + 0.5) * (3.14159265358979323846 / NQ);
            const double c1 = cos(th);
            double cm = 1.0, cc = c1;
            g_cosT[0 * NQ + t] = 1.0f;
            g_cosT[1 * NQ + t] = (float)c1;
            for (int j = 2; j < NC; j++) {
                const double cn = 2.0 * c1 * cc - cm;
                g_cosT[j * NQ + t] = (float)cn;
                cm = cc; cc = cn;
            }
        }
        return;
    }
    if (blockIdx.x == (N_E / TI1) + 1) {
        // F[p*NQ+q] = tanh(D*(x_p + x_q))
        __shared__ float xn[NQ];
        if (t < NQ) {
            const double th = (t + 0.5) * (3.14159265358979323846 / NQ);
            xn[t] = (float)cos(th);
        }
        __syncthreads();
        for (int idx = t; idx < NQ * NQ; idx += FSPLIT * HIDDEN) {
            const int p = idx >> 6, q = idx & 63;
            g_F[idx] = tanhf(DDOM * (xn[p] + xn[q]));
        }
        return;
    }

    const int h  = t & (HIDDEN - 1);
    const int fg = t >> 7;
    const int i0 = blockIdx.x * TI1;

    __shared__ float xs[TI1][N_IN];                      // 1 KB
    __shared__ float red[FSPLIT][2][TI1][HIDDEN];        // 16 KB

    if (t < TI1 * N_IN) xs[t >> 6][t & 63] = x[i0 * N_IN + t];
    __syncthreads();

    float a[TI1], b[TI1];
    #pragma unroll
    for (int k = 0; k < TI1; k++) { a[k] = 0.0f; b[k] = 0.0f; }

    const int fbase = fg * FPT;
    #pragma unroll
    for (int ff = 0; ff < FPT; ff++) {
        const int f = fbase + ff;
        const float wa = W1[f * HIDDEN + h];
        const float wb = W1[(N_IN + f) * HIDDEN + h];
        #pragma unroll
        for (int k = 0; k < TI1; k++) {
            const float xv = xs[k][f];
            a[k] = fmaf(xv, wa, a[k]);
            b[k] = fmaf(xv, wb, b[k]);
        }
    }

    #pragma unroll
    for (int k = 0; k < TI1; k++) {
        red[fg][0][k][h] = a[k];
        red[fg][1][k][h] = b[k];
    }
    __syncthreads();

    if (fg == 0) {
        const float bb = b1[h];
        #pragma unroll
        for (int k = 0; k < TI1; k++) {
            float av = a[k] + red[1][0][k][h] + red[2][0][k][h] + red[3][0][k][h];
            float bv = b[k] + red[1][1][k][h] + red[2][1][k][h] + red[3][1][k][h];
            g_A[(i0 + k) * HIDDEN + h] = av + bb;
            g_B[(i0 + k) * HIDDEN + h] = bv;
        }
    }
}

// ---------------------------------------------------------------------------
// K2: separable 2D DCT -> C_jk. One block per j (NC x 64 threads).
// Double accumulation, chains broken 4-way for DFMA latency.
// ---------------------------------------------------------------------------
__global__ void __launch_bounds__(NQ) k2_dct()
{
    const int j = blockIdx.x;
    const int t = threadIdx.x;

    __shared__ double Gq[NQ];

    double g0 = 0.0, g1 = 0.0, g2 = 0.0, g3 = 0.0;
    #pragma unroll
    for (int p = 0; p < NQ; p += 4) {
        g0 += (double)g_F[(p + 0) * NQ + t] * (double)g_cosT[j * NQ + p + 0];
        g1 += (double)g_F[(p + 1) * NQ + t] * (double)g_cosT[j * NQ + p + 1];
        g2 += (double)g_F[(p + 2) * NQ + t] * (double)g_cosT[j * NQ + p + 2];
        g3 += (double)g_F[(p + 3) * NQ + t] * (double)g_cosT[j * NQ + p + 3];
    }
    Gq[t] = (g0 + g1) + (g2 + g3);
    __syncthreads();

    if (t < NC) {
        double c0 = 0.0, c1 = 0.0;
        #pragma unroll
        for (int q = 0; q < NQ; q += 2) {
            c0 += Gq[q]     * (double)g_cosT[t * NQ + q];
            c1 += Gq[q + 1] * (double)g_cosT[t * NQ + q + 1];
        }
        const double wj = (j == 0) ? 1.0 : 2.0;
        const double wk = (t == 0) ? 1.0 : 2.0;
        g_C[j * NC + t] = (float)((c0 + c1) * wj * wk / ((double)NQ * NQ));
    }
}

// ---------------------------------------------------------------------------
// K3: fused moments + reduce: M_k[h] = sum_p T_k(B~[p,h]); R_j[h] = sum_k C_jk M_k[h].
// One block per h, 512 threads, 2 p's per thread, warp-shuffle reduce.
// ---------------------------------------------------------------------------
__global__ void __launch_bounds__(512) k3_moments()
{
    const int h    = blockIdx.x;
    const int t    = threadIdx.x;
    const int lane = t & 31;
    const int wid  = t >> 5;              // 16 warps
    const float invD = 1.0f / DDOM;

    float m[NC];
    #pragma unroll
    for (int k = 0; k < NC; k++) m[k] = 0.0f;

    #pragma unroll
    for (int r = 0; r < 2; r++) {
        const int p = r * 512 + t;
        float xv = g_B[p * HIDDEN + h] * invD;
        xv = fminf(fmaxf(xv, -1.0f), 1.0f);
        float tp = 1.0f, tc = xv;
        m[0] += 1.0f;
        m[1] += xv;
        const float x2 = 2.0f * xv;
        #pragma unroll
        for (int k = 2; k < NC; k++) {
            const float tn = fmaf(x2, tc, -tp);
            m[k] += tn;
            tp = tc; tc = tn;
        }
    }

    __shared__ float warp_red[16][NC];
    __shared__ float Msh[NC];

    #pragma unroll
    for (int k = 0; k < NC; k++) {
        float v = m[k];
        v += __shfl_xor_sync(0xffffffff, v, 16);
        v += __shfl_xor_sync(0xffffffff, v, 8);
        v += __shfl_xor_sync(0xffffffff, v, 4);
        v += __shfl_xor_sync(0xffffffff, v, 2);
        v += __shfl_xor_sync(0xffffffff, v, 1);
        if (lane == 0) warp_red[wid][k] = v;
    }
    __syncthreads();

    if (t < NC) {
        float s = 0.0f;
        #pragma unroll
        for (int w = 0; w < 16; w++) s += warp_red[w][t];
        Msh[t] = s;
    }
    __syncthreads();

    if (t < NC) {
        float r0 = 0.0f, r1 = 0.0f;
        #pragma unroll
        for (int k = 0; k < NC - 1; k += 2) {
            r0 = fmaf(g_C[t * NC + k],     Msh[k],     r0);
            r1 = fmaf(g_C[t * NC + k + 1], Msh[k + 1], r1);
        }
        r0 = fmaf(g_C[t * NC + NC - 1], Msh[NC - 1], r0);
        g_R[t * HIDDEN + h] = r0 + r1;
    }
}

// ---------------------------------------------------------------------------
// K4: fused main. 512 blocks x 256 threads; block covers 2 i-rows.
// Thread = (h, i): single Chebyshev recurrence, latency hidden by ~28 warps/SM
// (occupancy fix for the 10.8%-occ bottleneck). Then self-term + W2 GEMV.
// ---------------------------------------------------------------------------
__global__ void __launch_bounds__(2 * HIDDEN) k4_main(
    const float* __restrict__ W2, const float* __restrict__ b2,
    float* __restrict__ out)
{
    const int t  = threadIdx.x;
    const int h  = t & (HIDDEN - 1);
    const int ig = t >> 7;                // 0..1: which i-row
    const int i0 = blockIdx.x * TI4;
    const int i  = i0 + ig;
    const float invD = 1.0f / DDOM;

    __shared__ float s2[HIDDEN][TI4];     // 1 KB
    __shared__ float po[2][TI4][OUTD];    // 2 KB

    // Chebyshev evaluation: one (i,h) per thread.
    const float araw = g_A[i * HIDDEN + h];
    float a = araw * invD;
    a = fminf(fmaxf(a, -1.0f), 1.0f);
    const float x2 = 2.0f * a;
    float tp = 1.0f, tc = a;
    float s = fmaf(g_R[1 * HIDDEN + h], a, g_R[0 * HIDDEN + h]);

    #pragma unroll
    for (int j = 2; j < NC; j++) {
        const float tn = fmaf(x2, tc, -tp);
        s = fmaf(g_R[j * HIDDEN + h], tn, s);
        tp = tc; tc = tn;
    }

    // self term + scale
    const float self_t = tanh_fast(araw + g_B[i * HIDDEN + h]);
    s2[h][ig] = (s - self_t) * (1.0f / (float)(N_E - 1));
    __syncthreads();

    // GEMV through W2: 4 groups of 64 threads = (half of hidden) x (i-row)
    const int o    = t & (OUTD - 1);
    const int grp  = t >> 6;              // 0..3
    const int il   = grp & 1;             // i-row
    const int half = grp >> 1;            // hidden half

    float acc = 0.0f;
    #pragma unroll 8
    for (int hh = 0; hh < HIDDEN / 2; hh++) {
        const int hid = half * (HIDDEN / 2) + hh;
        acc = fmaf(s2[hid][il], W2[hid * OUTD + o], acc);
    }
    po[half][il][o] = acc;
    __syncthreads();

    if (t < TI4 * OUTD) {
        const int oo = t & (OUTD - 1);
        const int ii = t >> 6;
        out[(i0 + ii) * OUTD + oo] = po[0][ii][oo] + po[1][ii][oo] + b2[oo];
    }
}

// ---------------------------------------------------------------------------
extern "C" void kernel_launch(void* const* d_in, const int* in_sizes, int n_in,
                              void* d_out, int out_size)
{
    // Map inputs by element count (all distinct): x=65536, W1=16384, b1=128,
    // W2=8192, b2=64.
    const float *x = nullptr, *W1 = nullptr, *b1 = nullptr, *W2 = nullptr, *b2 = nullptr;
    for (int i = 0; i < n_in; i++) {
        switch (in_sizes[i]) {
            case N_E * N_IN:          x  = (const float*)d_in[i]; break;
            case 2 * N_IN * HIDDEN:   W1 = (const float*)d_in[i]; break;
            case HIDDEN:              b1 = (const float*)d_in[i]; break;
            case HIDDEN * OUTD:       W2 = (const float*)d_in[i]; break;
            case OUTD:                b2 = (const float*)d_in[i]; break;
            default: break;
        }
    }
    float* out = (float*)d_out;

    k1_phase1_tables<<<N_E / TI1 + 2, FSPLIT * HIDDEN>>>(x, W1, b1);
    k2_dct<<<NC, NQ>>>();
    k3_moments<<<HIDDEN, 512>>>();
    k4_main<<<N_E / TI4, 2 * HIDDEN>>>(W2, b2, out);
}